// round 3
// baseline (speedup 1.0000x reference)
#include <cuda_runtime.h>

// Problem constants (baked per reference)
#define BC 32
#define HC 384
#define WC 384
#define CC 8
#define NPIX (BC * HC * WC)        // 4,718,592 pixels
#define NITER 5

// Tile geometry for the conv kernel
#define TW 32
#define TH 16
#define NTHREADS (TW * TH)          // 512
#define HW (TW + 6)                 // 38 (3-halo each side)
#define HH (TH + 6)                 // 22

// Scratch: q ping-pong + unary potentials (device globals; no cudaMalloc allowed)
__device__ __align__(16) float g_qA[(size_t)NPIX * CC];
__device__ __align__(16) float g_qB[(size_t)NPIX * CC];
__device__ __align__(16) float g_u [(size_t)NPIX * CC];

// ---- packed f32x2 helpers (ptxas will not auto-fuse; PTX only) ----
__device__ __forceinline__ unsigned long long pack2(float a, float b) {
    unsigned long long r;
    asm("mov.b64 %0, {%1, %2};" : "=l"(r) : "f"(a), "f"(b));
    return r;
}
__device__ __forceinline__ void unpack2(unsigned long long v, float& a, float& b) {
    asm("mov.b64 {%0, %1}, %2;" : "=f"(a), "=f"(b) : "l"(v));
}
__device__ __forceinline__ void fma2(unsigned long long& d,
                                     unsigned long long a, unsigned long long b) {
    asm("fma.rn.f32x2 %0, %1, %2, %0;" : "+l"(d) : "l"(a), "l"(b));
}

// ---------------------------------------------------------------------------
// init: q0 = softmax(x), u = -log(clip(q0, 1e-6, 1))
// ---------------------------------------------------------------------------
__global__ void init_kernel(const float* __restrict__ x) {
    size_t p = (size_t)blockIdx.x * blockDim.x + threadIdx.x;
    if (p >= (size_t)NPIX) return;
    float4 a = *(const float4*)(x + p * CC);
    float4 b = *(const float4*)(x + p * CC + 4);
    float v[8] = {a.x, a.y, a.z, a.w, b.x, b.y, b.z, b.w};
    float m = v[0];
#pragma unroll
    for (int c = 1; c < 8; ++c) m = fmaxf(m, v[c]);
    float e[8], s = 0.f;
#pragma unroll
    for (int c = 0; c < 8; ++c) { e[c] = __expf(v[c] - m); s += e[c]; }
    float r = __fdividef(1.0f, s);
    float q[8], u[8];
#pragma unroll
    for (int c = 0; c < 8; ++c) {
        q[c] = e[c] * r;
        u[c] = -__logf(fmaxf(q[c], 1e-6f));
    }
    *(float4*)(g_qA + p * CC)     = make_float4(q[0], q[1], q[2], q[3]);
    *(float4*)(g_qA + p * CC + 4) = make_float4(q[4], q[5], q[6], q[7]);
    *(float4*)(g_u  + p * CC)     = make_float4(u[0], u[1], u[2], u[3]);
    *(float4*)(g_u  + p * CC + 4) = make_float4(u[4], u[5], u[6], u[7]);
}

// ---------------------------------------------------------------------------
// One mean-field iteration, fully fused:
//   penalty = conv7x7(q, masked k)  [SAME, zero pad]
//   logits  = -(u + penalty)
//   y       = logits @ W + b
//   LAST ? write y : write softmax(y) as next q
// SRC=0: read g_qA (write g_qB); SRC=1: read g_qB (write g_qA)
// ---------------------------------------------------------------------------
template <int SRC, bool LAST>
__global__ __launch_bounds__(NTHREADS)
void iter_kernel(float* __restrict__ out_ext,
                 const float* __restrict__ kg,
                 const float* __restrict__ wg,
                 const float* __restrict__ bg) {
    __shared__ __align__(16) float s_q[HH][HW][CC];   // 26.75 KB
    __shared__ __align__(16) float s_k[49 * 64];      // 12.54 KB (diag pre-masked)
    __shared__ __align__(16) float s_w[64];
    __shared__ float s_b[8];

    const float* qin = SRC ? g_qB : g_qA;
    float* qout = LAST ? out_ext : (SRC ? g_qA : g_qB);

    const int tid = threadIdx.x;
    const int x0 = blockIdx.x * TW - 3;
    const int y0 = blockIdx.y * TH - 3;
    const float* qimg = qin + (size_t)blockIdx.z * HC * WC * CC;

    // masked kernel -> smem
    for (int i = tid; i < 49 * 64; i += NTHREADS) {
        int cout = i & 7, cin = (i >> 3) & 7;
        s_k[i] = (cin == cout) ? 0.f : kg[i];
    }
    if (tid < 64) s_w[tid] = wg[tid];
    if (tid < 8)  s_b[tid] = bg[tid];

    // q tile + halo -> smem (zero fill outside image)
    for (int i = tid; i < HH * HW * 2; i += NTHREADS) {
        int p = i >> 1, half = i & 1;
        int py = p / HW, px = p - py * HW;
        int gy = y0 + py, gx = x0 + px;
        float4 v = make_float4(0.f, 0.f, 0.f, 0.f);
        if ((unsigned)gy < (unsigned)HC && (unsigned)gx < (unsigned)WC)
            v = *(const float4*)(qimg + ((size_t)gy * WC + gx) * CC + half * 4);
        *(float4*)(&s_q[py][px][half * 4]) = v;
    }
    __syncthreads();

    const int tx = tid & (TW - 1);
    const int ty = tid >> 5;

    // penalty accumulation in packed f32x2: acc[p] holds couts {2p, 2p+1}
    unsigned long long acc0 = 0ull, acc1 = 0ull, acc2 = 0ull, acc3 = 0ull;
    const unsigned long long* sk2 = (const unsigned long long*)s_k;

#pragma unroll 1
    for (int dy = 0; dy < 7; ++dy) {
        const float* qrow = &s_q[ty + dy][tx][0];
        const unsigned long long* krow = sk2 + dy * 7 * 32;
#pragma unroll
        for (int dx = 0; dx < 7; ++dx) {
            float4 qa = *(const float4*)(qrow + dx * CC);
            float4 qb = *(const float4*)(qrow + dx * CC + 4);
            const unsigned long long* kk = krow + dx * 32;
            float qv[8] = {qa.x, qa.y, qa.z, qa.w, qb.x, qb.y, qb.z, qb.w};
#pragma unroll
            for (int cin = 0; cin < 8; ++cin) {
                unsigned long long q2 = pack2(qv[cin], qv[cin]);
                ulonglong2 ka = *(const ulonglong2*)(kk + cin * 4);
                ulonglong2 kb = *(const ulonglong2*)(kk + cin * 4 + 2);
                fma2(acc0, q2, ka.x);
                fma2(acc1, q2, ka.y);
                fma2(acc2, q2, kb.x);
                fma2(acc3, q2, kb.y);
            }
        }
    }

    float pen[8];
    unpack2(acc0, pen[0], pen[1]);
    unpack2(acc1, pen[2], pen[3]);
    unpack2(acc2, pen[4], pen[5]);
    unpack2(acc3, pen[6], pen[7]);

    const int gx = x0 + 3 + tx;
    const int gy = y0 + 3 + ty;
    const size_t poff = (((size_t)blockIdx.z * HC + gy) * WC + gx) * CC;

    float4 ua = *(const float4*)(g_u + poff);
    float4 ub = *(const float4*)(g_u + poff + 4);
    float uu[8] = {ua.x, ua.y, ua.z, ua.w, ub.x, ub.y, ub.z, ub.w};
    float lg[8];
#pragma unroll
    for (int c = 0; c < 8; ++c) lg[c] = -(uu[c] + pen[c]);

    // y = lg @ W + b, packed over output pairs
    unsigned long long yac0 = pack2(s_b[0], s_b[1]);
    unsigned long long yac1 = pack2(s_b[2], s_b[3]);
    unsigned long long yac2 = pack2(s_b[4], s_b[5]);
    unsigned long long yac3 = pack2(s_b[6], s_b[7]);
    const unsigned long long* sw2 = (const unsigned long long*)s_w;
#pragma unroll
    for (int c = 0; c < 8; ++c) {
        unsigned long long l2 = pack2(lg[c], lg[c]);
        ulonglong2 wa = *(const ulonglong2*)(sw2 + c * 4);
        ulonglong2 wb = *(const ulonglong2*)(sw2 + c * 4 + 2);
        fma2(yac0, l2, wa.x);
        fma2(yac1, l2, wa.y);
        fma2(yac2, l2, wb.x);
        fma2(yac3, l2, wb.y);
    }
    float y[8];
    unpack2(yac0, y[0], y[1]);
    unpack2(yac1, y[2], y[3]);
    unpack2(yac2, y[4], y[5]);
    unpack2(yac3, y[6], y[7]);

    if (LAST) {
        *(float4*)(qout + poff)     = make_float4(y[0], y[1], y[2], y[3]);
        *(float4*)(qout + poff + 4) = make_float4(y[4], y[5], y[6], y[7]);
    } else {
        float m = y[0];
#pragma unroll
        for (int c = 1; c < 8; ++c) m = fmaxf(m, y[c]);
        float e[8], s = 0.f;
#pragma unroll
        for (int c = 0; c < 8; ++c) { e[c] = __expf(y[c] - m); s += e[c]; }
        float r = __fdividef(1.0f, s);
        *(float4*)(qout + poff)     = make_float4(e[0]*r, e[1]*r, e[2]*r, e[3]*r);
        *(float4*)(qout + poff + 4) = make_float4(e[4]*r, e[5]*r, e[6]*r, e[7]*r);
    }
}

// ---------------------------------------------------------------------------
extern "C" void kernel_launch(void* const* d_in, const int* in_sizes, int n_in,
                              void* d_out, int out_size) {
    const float* x  = (const float*)d_in[0];   // [32,384,384,8]
    const float* kg = (const float*)d_in[1];   // [7,7,8,8]
    const float* wg = (const float*)d_in[2];   // [8,8]
    const float* bg = (const float*)d_in[3];   // [8]
    float* out = (float*)d_out;
    (void)in_sizes; (void)n_in; (void)out_size;

    init_kernel<<<NPIX / 256, 256>>>(x);

    dim3 grid(WC / TW, HC / TH, BC);  // 12 x 24 x 32
    // 5 iterations, ping-pong qA <-> qB; last writes raw logits to d_out
    iter_kernel<0, false><<<grid, NTHREADS>>>(nullptr, kg, wg, bg);  // qA -> qB
    iter_kernel<1, false><<<grid, NTHREADS>>>(nullptr, kg, wg, bg);  // qB -> qA
    iter_kernel<0, false><<<grid, NTHREADS>>>(nullptr, kg, wg, bg);  // qA -> qB
    iter_kernel<1, false><<<grid, NTHREADS>>>(nullptr, kg, wg, bg);  // qB -> qA
    iter_kernel<0, true ><<<grid, NTHREADS>>>(out, kg, wg, bg);      // qA -> out
}

// round 4
// speedup vs baseline: 2.3035x; 2.3035x over previous
#include <cuda_runtime.h>

// Problem constants (baked per reference)
#define BC 32
#define HC 384
#define WC 384
#define CC 8
#define NPIX (BC * HC * WC)        // 4,718,592 pixels
#define NITER 5

// Tile geometry: block (32,4) threads, each thread computes 4 outputs in y.
// Tile = 32 wide x 16 tall. Halo = 3 each side.
#define TW 32
#define TTH 16                      // tile height (outputs)
#define OPT 4                       // outputs per thread (in y)
#define HW (TW + 6)                 // 38
#define HH (TTH + 6)                // 22
#define NTHREADS (TW * OPT)         // 128

// Scratch: q ping-pong + unary potentials (device globals; no cudaMalloc allowed)
__device__ __align__(16) float g_qA[(size_t)NPIX * CC];
__device__ __align__(16) float g_qB[(size_t)NPIX * CC];
__device__ __align__(16) float g_u [(size_t)NPIX * CC];

// ---- packed f32x2 helpers (ptxas will not auto-fuse; PTX only) ----
__device__ __forceinline__ unsigned long long pack2(float a, float b) {
    unsigned long long r;
    asm("mov.b64 %0, {%1, %2};" : "=l"(r) : "f"(a), "f"(b));
    return r;
}
__device__ __forceinline__ void unpack2(unsigned long long v, float& a, float& b) {
    asm("mov.b64 {%0, %1}, %2;" : "=f"(a), "=f"(b) : "l"(v));
}
__device__ __forceinline__ void fma2(unsigned long long& d,
                                     unsigned long long a, unsigned long long b) {
    asm("fma.rn.f32x2 %0, %1, %2, %0;" : "+l"(d) : "l"(a), "l"(b));
}

// ---------------------------------------------------------------------------
// init: q0 = softmax(x), u = -log(clip(q0, 1e-6, 1))
// ---------------------------------------------------------------------------
__global__ void init_kernel(const float* __restrict__ x) {
    size_t p = (size_t)blockIdx.x * blockDim.x + threadIdx.x;
    if (p >= (size_t)NPIX) return;
    float4 a = *(const float4*)(x + p * CC);
    float4 b = *(const float4*)(x + p * CC + 4);
    float v[8] = {a.x, a.y, a.z, a.w, b.x, b.y, b.z, b.w};
    float m = v[0];
#pragma unroll
    for (int c = 1; c < 8; ++c) m = fmaxf(m, v[c]);
    float e[8], s = 0.f;
#pragma unroll
    for (int c = 0; c < 8; ++c) { e[c] = __expf(v[c] - m); s += e[c]; }
    float r = __fdividef(1.0f, s);
    float q[8], u[8];
#pragma unroll
    for (int c = 0; c < 8; ++c) {
        q[c] = e[c] * r;
        u[c] = -__logf(fmaxf(q[c], 1e-6f));
    }
    *(float4*)(g_qA + p * CC)     = make_float4(q[0], q[1], q[2], q[3]);
    *(float4*)(g_qA + p * CC + 4) = make_float4(q[4], q[5], q[6], q[7]);
    *(float4*)(g_u  + p * CC)     = make_float4(u[0], u[1], u[2], u[3]);
    *(float4*)(g_u  + p * CC + 4) = make_float4(u[4], u[5], u[6], u[7]);
}

// ---------------------------------------------------------------------------
// One mean-field iteration, fully fused. Channel-planar smem q for
// conflict-free scalar reads; each thread computes OPT outputs stacked in y so
// every broadcast k load is amortized OPT times.
// ---------------------------------------------------------------------------
template <int SRC, bool LAST>
__global__ __launch_bounds__(NTHREADS)
void iter_kernel(float* __restrict__ out_ext,
                 const float* __restrict__ kg,
                 const float* __restrict__ wg,
                 const float* __restrict__ bg) {
    __shared__ float s_q[CC][HH][HW];              // planar: 8*22*38*4 = 26.1 KB
    __shared__ __align__(16) float s_k[49 * 64];   // 12.25 KB (diag pre-masked)
    __shared__ __align__(16) float s_w[64];
    __shared__ float s_b[8];

    const float* qin = SRC ? g_qB : g_qA;
    float* qout = LAST ? out_ext : (SRC ? g_qA : g_qB);

    const int tx  = threadIdx.x;         // 0..31
    const int ty  = threadIdx.y;         // 0..3
    const int tid = ty * TW + tx;
    const int x0 = blockIdx.x * TW - 3;
    const int y0 = blockIdx.y * TTH - 3;
    const float* qimg = qin + (size_t)blockIdx.z * HC * WC * CC;

    // masked kernel -> smem
    for (int i = tid; i < 49 * 64; i += NTHREADS) {
        int cout = i & 7, cin = (i >> 3) & 7;
        s_k[i] = (cin == cout) ? 0.f : kg[i];
    }
    if (tid < 64) s_w[tid] = wg[tid];
    if (tid < 8)  s_b[tid] = bg[tid];

    // q tile + halo -> planar smem (zero fill outside image).
    // Consecutive threads take consecutive px: gmem reads coalesced,
    // STS.32 lane stride 4B -> conflict-free.
    for (int i = tid; i < HH * HW; i += NTHREADS) {
        int py = i / HW, px = i - py * HW;
        int gy = y0 + py, gx = x0 + px;
        float4 a = make_float4(0.f, 0.f, 0.f, 0.f);
        float4 b = a;
        if ((unsigned)gy < (unsigned)HC && (unsigned)gx < (unsigned)WC) {
            const float* src = qimg + ((size_t)gy * WC + gx) * CC;
            a = *(const float4*)(src);
            b = *(const float4*)(src + 4);
        }
        s_q[0][py][px] = a.x; s_q[1][py][px] = a.y;
        s_q[2][py][px] = a.z; s_q[3][py][px] = a.w;
        s_q[4][py][px] = b.x; s_q[5][py][px] = b.y;
        s_q[6][py][px] = b.z; s_q[7][py][px] = b.w;
    }
    __syncthreads();

    // Accumulators: acc[o][p] = couts {2p,2p+1} of output row (ty*OPT + o)
    unsigned long long acc[OPT][4];
#pragma unroll
    for (int o = 0; o < OPT; ++o)
#pragma unroll
        for (int p = 0; p < 4; ++p) acc[o][p] = 0ull;

    const int rbase = ty * OPT;   // first q row this thread's outputs touch

#pragma unroll 1
    for (int dx = 0; dx < 7; ++dx) {
#pragma unroll 1
        for (int cin = 0; cin < CC; ++cin) {
            // q column (rows rbase .. rbase+OPT+5), packed duplicated
            unsigned long long q2[OPT + 6];
#pragma unroll
            for (int r = 0; r < OPT + 6; ++r) {
                float v = s_q[cin][rbase + r][tx + dx];
                q2[r] = pack2(v, v);
            }
#pragma unroll
            for (int dy = 0; dy < 7; ++dy) {
                // k[dy][dx][cin][0..7] — warp-uniform broadcast loads
                const unsigned long long* kk =
                    (const unsigned long long*)(s_k + (((dy * 7) + dx) * 8 + cin) * 8);
                ulonglong2 ka = *(const ulonglong2*)(kk);
                ulonglong2 kb = *(const ulonglong2*)(kk + 2);
#pragma unroll
                for (int o = 0; o < OPT; ++o) {
                    fma2(acc[o][0], q2[dy + o], ka.x);
                    fma2(acc[o][1], q2[dy + o], ka.y);
                    fma2(acc[o][2], q2[dy + o], kb.x);
                    fma2(acc[o][3], q2[dy + o], kb.y);
                }
            }
        }
    }

    // Epilogue per output row
    const int gx = blockIdx.x * TW + tx;
    const unsigned long long* sw2 = (const unsigned long long*)s_w;

#pragma unroll
    for (int o = 0; o < OPT; ++o) {
        float pen[8];
        unpack2(acc[o][0], pen[0], pen[1]);
        unpack2(acc[o][1], pen[2], pen[3]);
        unpack2(acc[o][2], pen[4], pen[5]);
        unpack2(acc[o][3], pen[6], pen[7]);

        const int gy = blockIdx.y * TTH + rbase + o;
        const size_t poff = (((size_t)blockIdx.z * HC + gy) * WC + gx) * CC;

        float4 ua = *(const float4*)(g_u + poff);
        float4 ub = *(const float4*)(g_u + poff + 4);
        float uu[8] = {ua.x, ua.y, ua.z, ua.w, ub.x, ub.y, ub.z, ub.w};
        float lg[8];
#pragma unroll
        for (int c = 0; c < 8; ++c) lg[c] = -(uu[c] + pen[c]);

        // y = lg @ W + b (packed over cout pairs)
        unsigned long long yac0 = pack2(s_b[0], s_b[1]);
        unsigned long long yac1 = pack2(s_b[2], s_b[3]);
        unsigned long long yac2 = pack2(s_b[4], s_b[5]);
        unsigned long long yac3 = pack2(s_b[6], s_b[7]);
#pragma unroll
        for (int c = 0; c < 8; ++c) {
            unsigned long long l2 = pack2(lg[c], lg[c]);
            ulonglong2 wa = *(const ulonglong2*)(sw2 + c * 4);
            ulonglong2 wb = *(const ulonglong2*)(sw2 + c * 4 + 2);
            fma2(yac0, l2, wa.x);
            fma2(yac1, l2, wa.y);
            fma2(yac2, l2, wb.x);
            fma2(yac3, l2, wb.y);
        }
        float y[8];
        unpack2(yac0, y[0], y[1]);
        unpack2(yac1, y[2], y[3]);
        unpack2(yac2, y[4], y[5]);
        unpack2(yac3, y[6], y[7]);

        if (LAST) {
            *(float4*)(qout + poff)     = make_float4(y[0], y[1], y[2], y[3]);
            *(float4*)(qout + poff + 4) = make_float4(y[4], y[5], y[6], y[7]);
        } else {
            float m = y[0];
#pragma unroll
            for (int c = 1; c < 8; ++c) m = fmaxf(m, y[c]);
            float e[8], s = 0.f;
#pragma unroll
            for (int c = 0; c < 8; ++c) { e[c] = __expf(y[c] - m); s += e[c]; }
            float r = __fdividef(1.0f, s);
            *(float4*)(qout + poff)     = make_float4(e[0]*r, e[1]*r, e[2]*r, e[3]*r);
            *(float4*)(qout + poff + 4) = make_float4(e[4]*r, e[5]*r, e[6]*r, e[7]*r);
        }
    }
}

// ---------------------------------------------------------------------------
extern "C" void kernel_launch(void* const* d_in, const int* in_sizes, int n_in,
                              void* d_out, int out_size) {
    const float* x  = (const float*)d_in[0];   // [32,384,384,8]
    const float* kg = (const float*)d_in[1];   // [7,7,8,8]
    const float* wg = (const float*)d_in[2];   // [8,8]
    const float* bg = (const float*)d_in[3];   // [8]
    float* out = (float*)d_out;
    (void)in_sizes; (void)n_in; (void)out_size;

    init_kernel<<<NPIX / 256, 256>>>(x);

    dim3 block(TW, OPT);               // (32,4) = 128 threads
    dim3 grid(WC / TW, HC / TTH, BC);  // 12 x 24 x 32
    // 5 iterations, ping-pong qA <-> qB; last writes raw logits to d_out
    iter_kernel<0, false><<<grid, block>>>(nullptr, kg, wg, bg);  // qA -> qB
    iter_kernel<1, false><<<grid, block>>>(nullptr, kg, wg, bg);  // qB -> qA
    iter_kernel<0, false><<<grid, block>>>(nullptr, kg, wg, bg);  // qA -> qB
    iter_kernel<1, false><<<grid, block>>>(nullptr, kg, wg, bg);  // qB -> qA
    iter_kernel<0, true ><<<grid, block>>>(out, kg, wg, bg);      // qA -> out
}